// round 2
// baseline (speedup 1.0000x reference)
#include <cuda_runtime.h>
#include <math.h>
#include <stdint.h>

// Problem constants
#define BB   8
#define SS   1024
#define DD   1024
#define HH   16
#define KD   64
#define VD   64
#define MTOT (BB*SS)             // 8192
#define NELEM_PER_BATCH (SS*DD)  // 1048576

// ---------------------------------------------------------------------------
// Scratch (device globals; no dynamic allocation allowed)
// ---------------------------------------------------------------------------
__device__ float g_Q[(size_t)BB*HH*SS*KD];    // [b,h,s,kd]  32 MiB
__device__ float g_K[(size_t)BB*HH*SS*KD];    // [b,h,s,kd]  32 MiB
__device__ float g_V[(size_t)BB*HH*SS*VD];    // [b,h,s,vd]  32 MiB
__device__ float g_Ctx[(size_t)MTOT*DD];      // [m, h*64+vd] 32 MiB
__device__ float g_Y[(size_t)MTOT*DD];        // pre-LN y     32 MiB
__device__ float g_psum[512];                 // per-CTA partials (O-proj grid 8x64)
__device__ float g_psq[512];
__device__ float g_mean[BB];
__device__ float g_rstd[BB];

// ---------------------------------------------------------------------------
// Tiled SGEMM: C[m,n] = sum_k A[m,k] * W[n,k] (+ epilogue)
//   A row-major [Mtot,1024], W row-major [N,1024]. 128x128 tile, BK=16,
//   8x8 microtile per thread, register prefetch of the next k-slab.
//   EPI 0: QK projection -> scatter to g_Q / g_K (+bias)
//   EPI 1: V  projection -> scatter to g_V (+bias)
//   EPI 2: O  projection -> +bias +residual(x) -> g_Y, CTA partial sum/sumsq
// ---------------------------------------------------------------------------
template<int EPI>
__global__ __launch_bounds__(256)
void gemm_k(const float* __restrict__ X, const float* __restrict__ W,
            const float* __restrict__ bias)
{
    __shared__ float As[16][132];
    __shared__ float Bs[16][132];
    __shared__ float rs[256];
    __shared__ float rq[256];

    const int tid = threadIdx.x;
    const int bm  = blockIdx.y * 128;
    const int bn  = blockIdx.x * 128;

    const float* A = (EPI == 2) ? g_Ctx : X;

    const int lr = tid >> 2;          // 0..63
    const int lc = (tid & 3) * 4;     // 0,4,8,12

    const float* aptr0 = A + (size_t)(bm + lr)      * 1024 + lc;
    const float* aptr1 = A + (size_t)(bm + lr + 64) * 1024 + lc;
    const float* bptr0 = W + (size_t)(bn + lr)      * 1024 + lc;
    const float* bptr1 = W + (size_t)(bn + lr + 64) * 1024 + lc;

    float acc[8][8];
#pragma unroll
    for (int i = 0; i < 8; i++)
#pragma unroll
        for (int j = 0; j < 8; j++) acc[i][j] = 0.f;

    const int ty = tid >> 4;   // 0..15
    const int tx = tid & 15;   // 0..15

    float4 a0 = *(const float4*)(aptr0);
    float4 a1 = *(const float4*)(aptr1);
    float4 b0 = *(const float4*)(bptr0);
    float4 b1 = *(const float4*)(bptr1);

#pragma unroll 1
    for (int kt = 0; kt < 1024; kt += 16) {
        As[lc+0][lr]    = a0.x; As[lc+1][lr]    = a0.y; As[lc+2][lr]    = a0.z; As[lc+3][lr]    = a0.w;
        As[lc+0][lr+64] = a1.x; As[lc+1][lr+64] = a1.y; As[lc+2][lr+64] = a1.z; As[lc+3][lr+64] = a1.w;
        Bs[lc+0][lr]    = b0.x; Bs[lc+1][lr]    = b0.y; Bs[lc+2][lr]    = b0.z; Bs[lc+3][lr]    = b0.w;
        Bs[lc+0][lr+64] = b1.x; Bs[lc+1][lr+64] = b1.y; Bs[lc+2][lr+64] = b1.z; Bs[lc+3][lr+64] = b1.w;
        __syncthreads();

        if (kt + 16 < 1024) {    // prefetch next k-slab into registers
            a0 = *(const float4*)(aptr0 + kt + 16);
            a1 = *(const float4*)(aptr1 + kt + 16);
            b0 = *(const float4*)(bptr0 + kt + 16);
            b1 = *(const float4*)(bptr1 + kt + 16);
        }

#pragma unroll
        for (int kk = 0; kk < 16; kk++) {
            float4 xa0 = *(const float4*)&As[kk][ty*4];
            float4 xa1 = *(const float4*)&As[kk][64 + ty*4];
            float4 xb0 = *(const float4*)&Bs[kk][tx*4];
            float4 xb1 = *(const float4*)&Bs[kk][64 + tx*4];
            float av[8] = {xa0.x, xa0.y, xa0.z, xa0.w, xa1.x, xa1.y, xa1.z, xa1.w};
            float bv[8] = {xb0.x, xb0.y, xb0.z, xb0.w, xb1.x, xb1.y, xb1.z, xb1.w};
#pragma unroll
            for (int i = 0; i < 8; i++)
#pragma unroll
                for (int j = 0; j < 8; j++)
                    acc[i][j] = fmaf(av[i], bv[j], acc[i][j]);
        }
        __syncthreads();
    }

    // ---------------- epilogue ----------------
    float lsum = 0.f, lsq = 0.f;
#pragma unroll
    for (int i = 0; i < 8; i++) {
        const int m    = bm + ((i < 4) ? (ty*4 + i) : (64 + ty*4 + (i-4)));
        const int bidx = m >> 10;        // batch
        const int si   = m & 1023;       // seq index
#pragma unroll
        for (int j = 0; j < 8; j++) {
            const int n = bn + ((j < 4) ? (tx*4 + j) : (64 + tx*4 + (j-4)));
            float val = acc[i][j] + bias[n];
            if (EPI == 0) {
                // n = kd*32 + p*16 + h   (qk reshape (b,s,KD,2,H))
                const int kd  = n >> 5;
                const int rem = n & 31;
                const int h   = rem & 15;
                const size_t dst = (((size_t)bidx*HH + h)*SS + si)*KD + kd;
                if (rem < 16) g_Q[dst] = val; else g_K[dst] = val;
            } else if (EPI == 1) {
                // n = vd*16 + h          (v reshape (b,s,VD,H))
                const int vd = n >> 4;
                const int h  = n & 15;
                g_V[(((size_t)bidx*HH + h)*SS + si)*VD + vd] = val;
            } else {
                val += X[(size_t)m*1024 + n];     // residual
                g_Y[(size_t)m*1024 + n] = val;
                lsum += val;
                lsq  += val * val;
            }
        }
    }

    if (EPI == 2) {
        rs[tid] = lsum; rq[tid] = lsq;
        __syncthreads();
#pragma unroll
        for (int s = 128; s > 0; s >>= 1) {
            if (tid < s) { rs[tid] += rs[tid+s]; rq[tid] += rq[tid+s]; }
            __syncthreads();
        }
        if (tid == 0) {
            const int p = blockIdx.y * 8 + blockIdx.x;   // grid (8,64) -> 512 partials
            g_psum[p] = rs[0];
            g_psq[p]  = rq[0];
        }
    }
}

// ---------------------------------------------------------------------------
// Fused flash-style attention. One CTA = (b, h, 64-row query tile), 256 thr.
// Streams 32-key tiles with online softmax.
//   Scores: thread (tx=tid&7, ty=tid>>3) owns rows {2ty,2ty+1} x cols {4tx..4tx+3}
//   Output: thread owns rows {2ty,2ty+1} x vd cols {8tx..8tx+7}
// ---------------------------------------------------------------------------
__global__ __launch_bounds__(256)
void attn_k()
{
    __shared__ float Qs [64][68];   // [row][kd], pre-scaled by 1/8
    __shared__ float KsT[64][36];   // transposed: [kd][key]
    __shared__ float Vs [32][68];   // [key][vd]
    __shared__ float Ps [64][36];   // probabilities tile

    const int tid = threadIdx.x;
    const int qt  = blockIdx.x;     // query tile 0..15
    const int h   = blockIdx.y;
    const int b   = blockIdx.z;
    const size_t bh_off = ((size_t)b*HH + h) * SS * KD;
    const float* Qg = g_Q + bh_off + (size_t)qt*64*KD;
    const float* Kg = g_K + bh_off;
    const float* Vg = g_V + bh_off;

    // Load + scale Q tile (64x64)
    {
        const int r = tid >> 2;
        const int c = (tid & 3) * 4;              // float4 index
        const float4* src = (const float4*)(Qg + (size_t)r*KD);
#pragma unroll
        for (int q = 0; q < 4; q++) {
            float4 v = src[c + q];
            v.x *= 0.125f; v.y *= 0.125f; v.z *= 0.125f; v.w *= 0.125f;
            *(float4*)&Qs[r][(c + q)*4] = v;
        }
    }

    const int tx = tid & 7;
    const int ty = tid >> 3;

    float mi[2] = {-1e30f, -1e30f};
    float li[2] = {0.f, 0.f};
    float o[2][8];
#pragma unroll
    for (int i = 0; i < 2; i++)
#pragma unroll
        for (int c = 0; c < 8; c++) o[i][c] = 0.f;

#pragma unroll 1
    for (int jt = 0; jt < SS; jt += 32) {
        // global loads first (overlap previous tile's PV compute)
        const int r = tid >> 3;              // 0..31
        const int c = (tid & 7) * 2;         // float4 idx
        const float4* kp = (const float4*)(Kg + (size_t)(jt + r)*KD);
        const float4* vp = (const float4*)(Vg + (size_t)(jt + r)*KD);
        float4 kv0 = kp[c], kv1 = kp[c+1];
        float4 vv0 = vp[c], vv1 = vp[c+1];

        __syncthreads();   // prior PV reads done
        // K stored transposed for conflict-free score fragments
        KsT[c*4+0][r] = kv0.x; KsT[c*4+1][r] = kv0.y; KsT[c*4+2][r] = kv0.z; KsT[c*4+3][r] = kv0.w;
        KsT[c*4+4][r] = kv1.x; KsT[c*4+5][r] = kv1.y; KsT[c*4+6][r] = kv1.z; KsT[c*4+7][r] = kv1.w;
        *(float4*)&Vs[r][c*4]     = vv0;
        *(float4*)&Vs[r][c*4 + 4] = vv1;
        __syncthreads();

        // ---- scores: s[2][4] over 64-dim dot ----
        float s[2][4];
#pragma unroll
        for (int i = 0; i < 2; i++)
#pragma unroll
            for (int j = 0; j < 4; j++) s[i][j] = 0.f;

        const float* q0p = &Qs[ty*2][0];
        const float* q1p = &Qs[ty*2 + 1][0];
#pragma unroll
        for (int k = 0; k < 64; k++) {
            const float4 kk4 = *(const float4*)&KsT[k][tx*4];
            const float q0 = q0p[k], q1 = q1p[k];
            s[0][0] = fmaf(q0, kk4.x, s[0][0]); s[0][1] = fmaf(q0, kk4.y, s[0][1]);
            s[0][2] = fmaf(q0, kk4.z, s[0][2]); s[0][3] = fmaf(q0, kk4.w, s[0][3]);
            s[1][0] = fmaf(q1, kk4.x, s[1][0]); s[1][1] = fmaf(q1, kk4.y, s[1][1]);
            s[1][2] = fmaf(q1, kk4.z, s[1][2]); s[1][3] = fmaf(q1, kk4.w, s[1][3]);
        }

        // ---- online softmax (row groups of 8 lanes) ----
#pragma unroll
        for (int ii = 0; ii < 2; ii++) {
            float mx = fmaxf(fmaxf(s[ii][0], s[ii][1]), fmaxf(s[ii][2], s[ii][3]));
            mx = fmaxf(mx, __shfl_xor_sync(0xffffffffu, mx, 1, 8));
            mx = fmaxf(mx, __shfl_xor_sync(0xffffffffu, mx, 2, 8));
            mx = fmaxf(mx, __shfl_xor_sync(0xffffffffu, mx, 4, 8));
            const float mnew = fmaxf(mi[ii], mx);
            const float corr = __expf(mi[ii] - mnew);
            float ps = 0.f;
#pragma unroll
            for (int j = 0; j < 4; j++) {
                const float p = __expf(s[ii][j] - mnew);
                Ps[ty*2 + ii][tx*4 + j] = p;
                ps += p;
            }
            ps += __shfl_xor_sync(0xffffffffu, ps, 1, 8);
            ps += __shfl_xor_sync(0xffffffffu, ps, 2, 8);
            ps += __shfl_xor_sync(0xffffffffu, ps, 4, 8);
            li[ii] = li[ii]*corr + ps;
            mi[ii] = mnew;
#pragma unroll
            for (int cc = 0; cc < 8; cc++) o[ii][cc] *= corr;
        }
        __syncthreads();

        // ---- PV: o += P(64x32) @ V(32x64) ----
#pragma unroll
        for (int j = 0; j < 32; j++) {
            const float p0 = Ps[ty*2][j];
            const float p1 = Ps[ty*2 + 1][j];
            const float4 v0 = *(const float4*)&Vs[j][tx*8];
            const float4 v1 = *(const float4*)&Vs[j][tx*8 + 4];
            o[0][0] = fmaf(p0, v0.x, o[0][0]); o[0][1] = fmaf(p0, v0.y, o[0][1]);
            o[0][2] = fmaf(p0, v0.z, o[0][2]); o[0][3] = fmaf(p0, v0.w, o[0][3]);
            o[0][4] = fmaf(p0, v1.x, o[0][4]); o[0][5] = fmaf(p0, v1.y, o[0][5]);
            o[0][6] = fmaf(p0, v1.z, o[0][6]); o[0][7] = fmaf(p0, v1.w, o[0][7]);
            o[1][0] = fmaf(p1, v0.x, o[1][0]); o[1][1] = fmaf(p1, v0.y, o[1][1]);
            o[1][2] = fmaf(p1, v0.z, o[1][2]); o[1][3] = fmaf(p1, v0.w, o[1][3]);
            o[1][4] = fmaf(p1, v1.x, o[1][4]); o[1][5] = fmaf(p1, v1.y, o[1][5]);
            o[1][6] = fmaf(p1, v1.z, o[1][6]); o[1][7] = fmaf(p1, v1.w, o[1][7]);
        }
    }

    // ---- write context: Ctx[b*1024+i][h*64 + vd] ----
#pragma unroll
    for (int ii = 0; ii < 2; ii++) {
        const float inv = 1.0f / li[ii];
        const int i = qt*64 + ty*2 + ii;
        const size_t base = ((size_t)(b*SS + i))*DD + h*64 + tx*8;
        float4 w0 = make_float4(o[ii][0]*inv, o[ii][1]*inv, o[ii][2]*inv, o[ii][3]*inv);
        float4 w1 = make_float4(o[ii][4]*inv, o[ii][5]*inv, o[ii][6]*inv, o[ii][7]*inv);
        *(float4*)&g_Ctx[base]     = w0;
        *(float4*)&g_Ctx[base + 4] = w1;
    }
}

// ---------------------------------------------------------------------------
// Per-batch LayerNorm stats from the 64 CTA partials per batch (deterministic)
// ---------------------------------------------------------------------------
__global__ void finalize_stats()
{
    const int t = threadIdx.x;
    if (t < BB) {
        double s = 0.0, q = 0.0;
        for (int i = 0; i < 64; i++) {
            s += (double)g_psum[t*64 + i];
            q += (double)g_psq [t*64 + i];
        }
        const double n = (double)NELEM_PER_BATCH;
        const double mean = s / n;
        const double var  = q / n - mean*mean;
        g_mean[t] = (float)mean;
        g_rstd[t] = (float)(1.0 / sqrt(var + 1e-5));
    }
}

// ---------------------------------------------------------------------------
// y = (y - mean) * rstd * ln_w + ln_b   (float4 vectorized)
// ---------------------------------------------------------------------------
__global__ __launch_bounds__(512)
void ln_apply(const float* __restrict__ lnw, const float* __restrict__ lnb,
              float* __restrict__ out)
{
    const size_t i4 = (size_t)blockIdx.x * 512 + threadIdx.x;  // float4 index
    const size_t i  = i4 * 4;
    const int b     = (int)(i >> 20);
    const size_t sd = i & (size_t)(NELEM_PER_BATCH - 1);

    const float4 y = *(const float4*)&g_Y[i];
    const float4 w = *(const float4*)&lnw[sd];
    const float4 c = *(const float4*)&lnb[sd];
    const float mu = g_mean[b];
    const float rs = g_rstd[b];

    float4 r;
    r.x = (y.x - mu)*rs*w.x + c.x;
    r.y = (y.y - mu)*rs*w.y + c.y;
    r.z = (y.z - mu)*rs*w.z + c.z;
    r.w = (y.w - mu)*rs*w.w + c.w;
    *(float4*)&out[i] = r;
}

// ---------------------------------------------------------------------------
extern "C" void kernel_launch(void* const* d_in, const int* in_sizes, int n_in,
                              void* d_out, int out_size)
{
    const float* x   = (const float*)d_in[0];
    const float* Wqk = (const float*)d_in[1];
    const float* bqk = (const float*)d_in[2];
    const float* Wv  = (const float*)d_in[3];
    const float* bv  = (const float*)d_in[4];
    const float* Wo  = (const float*)d_in[5];
    const float* bo  = (const float*)d_in[6];
    const float* lnw = (const float*)d_in[7];
    const float* lnb = (const float*)d_in[8];
    float* out = (float*)d_out;

    gemm_k<0><<<dim3(2048/128, MTOT/128), 256>>>(x, Wqk, bqk);   // q,k proj
    gemm_k<1><<<dim3(1024/128, MTOT/128), 256>>>(x, Wv,  bv);    // v proj
    attn_k  <<<dim3(SS/64, HH, BB), 256>>>();                    // context
    gemm_k<2><<<dim3(1024/128, MTOT/128), 256>>>(x, Wo,  bo);    // y + stats partials
    finalize_stats<<<1, 32>>>();
    ln_apply<<<(MTOT*DD/4)/512, 512>>>(lnw, lnb, out);
}

// round 3
// speedup vs baseline: 1.3085x; 1.3085x over previous
#include <cuda_runtime.h>
#include <math.h>
#include <stdint.h>

// Problem constants
#define BB   8
#define SS   1024
#define DD   1024
#define HH   16
#define KD   64
#define VD   64
#define MTOT (BB*SS)             // 8192
#define NELEM_PER_BATCH (SS*DD)  // 1048576

// ---------------------------------------------------------------------------
// Scratch (device globals; no dynamic allocation allowed)
// ---------------------------------------------------------------------------
__device__ float g_Q[(size_t)BB*HH*SS*KD];    // [b,h,s,kd]  32 MiB
__device__ float g_K[(size_t)BB*HH*SS*KD];    // [b,h,s,kd]  32 MiB
__device__ float g_V[(size_t)BB*HH*SS*VD];    // [b,h,s,vd]  32 MiB
__device__ float g_Ctx[(size_t)MTOT*DD];      // [m, h*64+vd] 32 MiB
__device__ float g_Y[(size_t)MTOT*DD];        // pre-LN y     32 MiB
__device__ float g_psum[512];                 // per-CTA partials (O-proj grid 8x64)
__device__ float g_psq[512];
__device__ float g_mean[BB];
__device__ float g_rstd[BB];

// ---------------------------------------------------------------------------
// TF32 helpers
// ---------------------------------------------------------------------------
__device__ __forceinline__ float f2tf(float f) {
    uint32_t u;
    asm("cvt.rna.tf32.f32 %0, %1;" : "=r"(u) : "f"(f));
    return __uint_as_float(u);   // tf32 bit pattern is a valid fp32 value
}

__device__ __forceinline__ void mma_tf32(float* c, const uint32_t* a, const uint32_t* b) {
    asm volatile(
        "mma.sync.aligned.m16n8k8.row.col.f32.tf32.tf32.f32 "
        "{%0,%1,%2,%3}, {%4,%5,%6,%7}, {%8,%9}, {%0,%1,%2,%3};"
        : "+f"(c[0]), "+f"(c[1]), "+f"(c[2]), "+f"(c[3])
        : "r"(a[0]), "r"(a[1]), "r"(a[2]), "r"(a[3]), "r"(b[0]), "r"(b[1]));
}

// ---------------------------------------------------------------------------
// TF32 tensor-core GEMM: C[m,n] = sum_k A[m,k] * W[n,k] (+ epilogue)
//   A row-major [Mtot,1024], W row-major [N,1024]. 128x128 tile, BK=16.
//   8 warps; each warp owns a 64x32 tile via 4x4 grid of m16n8k8 MMAs.
//   smem [row][k] with row stride 20 floats -> fragment LDS conflict-free.
//   EPI 0: QK projection -> scatter to g_Q / g_K (+bias)
//   EPI 1: V  projection -> scatter to g_V (+bias)
//   EPI 2: O  projection -> +bias +residual(x) -> g_Y, CTA partial sum/sumsq
// ---------------------------------------------------------------------------
#define SKS 20   // smem row stride (floats); (SKS/4) odd => conflict-free frag loads

template<int EPI>
__global__ __launch_bounds__(256, 2)
void gemm_mma(const float* __restrict__ X, const float* __restrict__ W,
              const float* __restrict__ bias)
{
    __shared__ float As[128][SKS];
    __shared__ float Bs[128][SKS];
    __shared__ float rs[256];
    __shared__ float rq[256];

    const int tid = threadIdx.x;
    const int bm  = blockIdx.y * 128;
    const int bn  = blockIdx.x * 128;

    const float* A = (EPI == 2) ? g_Ctx : X;

    // Loader mapping: thread loads float4 (along k) for rows lr and lr+64
    const int lr = tid >> 2;          // 0..63
    const int lc = (tid & 3) * 4;     // 0,4,8,12

    const float* aptr0 = A + (size_t)(bm + lr)      * 1024 + lc;
    const float* aptr1 = A + (size_t)(bm + lr + 64) * 1024 + lc;
    const float* bptr0 = W + (size_t)(bn + lr)      * 1024 + lc;
    const float* bptr1 = W + (size_t)(bn + lr + 64) * 1024 + lc;

    // MMA mapping
    const int warp = tid >> 5;
    const int lane = tid & 31;
    const int wm   = (warp >> 2) * 64;   // warp row offset (0 or 64)
    const int wn   = (warp & 3) * 32;    // warp col offset (0..96)
    const int gid  = lane >> 2;          // 0..7
    const int tig  = lane & 3;           // 0..3

    float acc[4][4][4];
#pragma unroll
    for (int mt = 0; mt < 4; mt++)
#pragma unroll
        for (int nt = 0; nt < 4; nt++)
#pragma unroll
            for (int e = 0; e < 4; e++) acc[mt][nt][e] = 0.f;

    float4 a0 = *(const float4*)(aptr0);
    float4 a1 = *(const float4*)(aptr1);
    float4 b0 = *(const float4*)(bptr0);
    float4 b1 = *(const float4*)(bptr1);

#pragma unroll 1
    for (int kt = 0; kt < 1024; kt += 16) {
        // Store current k-slab (converted to tf32 rounding) into smem [row][k]
        {
            float4 t;
            t.x = f2tf(a0.x); t.y = f2tf(a0.y); t.z = f2tf(a0.z); t.w = f2tf(a0.w);
            *(float4*)&As[lr][lc] = t;
            t.x = f2tf(a1.x); t.y = f2tf(a1.y); t.z = f2tf(a1.z); t.w = f2tf(a1.w);
            *(float4*)&As[lr + 64][lc] = t;
            t.x = f2tf(b0.x); t.y = f2tf(b0.y); t.z = f2tf(b0.z); t.w = f2tf(b0.w);
            *(float4*)&Bs[lr][lc] = t;
            t.x = f2tf(b1.x); t.y = f2tf(b1.y); t.z = f2tf(b1.z); t.w = f2tf(b1.w);
            *(float4*)&Bs[lr + 64][lc] = t;
        }
        __syncthreads();

        if (kt + 16 < 1024) {    // prefetch next k-slab into registers
            a0 = *(const float4*)(aptr0 + kt + 16);
            a1 = *(const float4*)(aptr1 + kt + 16);
            b0 = *(const float4*)(bptr0 + kt + 16);
            b1 = *(const float4*)(bptr1 + kt + 16);
        }

#pragma unroll
        for (int ks = 0; ks < 16; ks += 8) {
            uint32_t af[4][4];
            uint32_t bf[4][2];
#pragma unroll
            for (int mt = 0; mt < 4; mt++) {
                const int mrow = wm + mt * 16 + gid;
                af[mt][0] = __float_as_uint(As[mrow    ][ks + tig    ]);
                af[mt][1] = __float_as_uint(As[mrow + 8][ks + tig    ]);
                af[mt][2] = __float_as_uint(As[mrow    ][ks + tig + 4]);
                af[mt][3] = __float_as_uint(As[mrow + 8][ks + tig + 4]);
            }
#pragma unroll
            for (int nt = 0; nt < 4; nt++) {
                const int nrow = wn + nt * 8 + gid;
                bf[nt][0] = __float_as_uint(Bs[nrow][ks + tig    ]);
                bf[nt][1] = __float_as_uint(Bs[nrow][ks + tig + 4]);
            }
#pragma unroll
            for (int mt = 0; mt < 4; mt++)
#pragma unroll
                for (int nt = 0; nt < 4; nt++)
                    mma_tf32(acc[mt][nt], af[mt], bf[nt]);
        }
        __syncthreads();
    }

    // ---------------- epilogue ----------------
    float lsum = 0.f, lsq = 0.f;
#pragma unroll
    for (int mt = 0; mt < 4; mt++) {
#pragma unroll
        for (int e2 = 0; e2 < 2; e2++) {
            const int m    = bm + wm + mt * 16 + gid + e2 * 8;
            const int bidx = m >> 10;        // batch
            const int si   = m & 1023;       // seq index
#pragma unroll
            for (int nt = 0; nt < 4; nt++) {
#pragma unroll
                for (int e1 = 0; e1 < 2; e1++) {
                    const int n = bn + wn + nt * 8 + tig * 2 + e1;
                    float val = acc[mt][nt][e2 * 2 + e1] + bias[n];
                    if (EPI == 0) {
                        // n = kd*32 + p*16 + h   (qk reshape (b,s,KD,2,H))
                        const int kd  = n >> 5;
                        const int rem = n & 31;
                        const int h   = rem & 15;
                        const size_t dst = (((size_t)bidx*HH + h)*SS + si)*KD + kd;
                        if (rem < 16) g_Q[dst] = val; else g_K[dst] = val;
                    } else if (EPI == 1) {
                        // n = vd*16 + h          (v reshape (b,s,VD,H))
                        const int vd = n >> 4;
                        const int h  = n & 15;
                        g_V[(((size_t)bidx*HH + h)*SS + si)*VD + vd] = val;
                    } else {
                        val += X[(size_t)m*1024 + n];     // residual
                        g_Y[(size_t)m*1024 + n] = val;
                        lsum += val;
                        lsq  += val * val;
                    }
                }
            }
        }
    }

    if (EPI == 2) {
        rs[tid] = lsum; rq[tid] = lsq;
        __syncthreads();
#pragma unroll
        for (int s = 128; s > 0; s >>= 1) {
            if (tid < s) { rs[tid] += rs[tid+s]; rq[tid] += rq[tid+s]; }
            __syncthreads();
        }
        if (tid == 0) {
            const int p = blockIdx.y * 8 + blockIdx.x;   // grid (8,64) -> 512 partials
            g_psum[p] = rs[0];
            g_psq[p]  = rq[0];
        }
    }
}

// ---------------------------------------------------------------------------
// Fused flash-style attention (unchanged from R2 passing version).
// One CTA = (b, h, 64-row query tile), 256 threads; 32-key tiles, online softmax.
// ---------------------------------------------------------------------------
__global__ __launch_bounds__(256)
void attn_k()
{
    __shared__ float Qs [64][68];   // [row][kd], pre-scaled by 1/8
    __shared__ float KsT[64][36];   // transposed: [kd][key]
    __shared__ float Vs [32][68];   // [key][vd]
    __shared__ float Ps [64][36];   // probabilities tile

    const int tid = threadIdx.x;
    const int qt  = blockIdx.x;     // query tile 0..15
    const int h   = blockIdx.y;
    const int b   = blockIdx.z;
    const size_t bh_off = ((size_t)b*HH + h) * SS * KD;
    const float* Qg = g_Q + bh_off + (size_t)qt*64*KD;
    const float* Kg = g_K + bh_off;
    const float* Vg = g_V + bh_off;

    // Load + scale Q tile (64x64)
    {
        const int r = tid >> 2;
        const int c = (tid & 3) * 4;              // float4 index
        const float4* src = (const float4*)(Qg + (size_t)r*KD);
#pragma unroll
        for (int q = 0; q < 4; q++) {
            float4 v = src[c + q];
            v.x *= 0.125f; v.y *= 0.125f; v.z *= 0.125f; v.w *= 0.125f;
            *(float4*)&Qs[r][(c + q)*4] = v;
        }
    }

    const int tx = tid & 7;
    const int ty = tid >> 3;

    float mi[2] = {-1e30f, -1e30f};
    float li[2] = {0.f, 0.f};
    float o[2][8];
#pragma unroll
    for (int i = 0; i < 2; i++)
#pragma unroll
        for (int c = 0; c < 8; c++) o[i][c] = 0.f;

#pragma unroll 1
    for (int jt = 0; jt < SS; jt += 32) {
        const int r = tid >> 3;              // 0..31
        const int c = (tid & 7) * 2;         // float4 idx
        const float4* kp = (const float4*)(Kg + (size_t)(jt + r)*KD);
        const float4* vp = (const float4*)(Vg + (size_t)(jt + r)*KD);
        float4 kv0 = kp[c], kv1 = kp[c+1];
        float4 vv0 = vp[c], vv1 = vp[c+1];

        __syncthreads();   // prior PV reads done
        KsT[c*4+0][r] = kv0.x; KsT[c*4+1][r] = kv0.y; KsT[c*4+2][r] = kv0.z; KsT[c*4+3][r] = kv0.w;
        KsT[c*4+4][r] = kv1.x; KsT[c*4+5][r] = kv1.y; KsT[c*4+6][r] = kv1.z; KsT[c*4+7][r] = kv1.w;
        *(float4*)&Vs[r][c*4]     = vv0;
        *(float4*)&Vs[r][c*4 + 4] = vv1;
        __syncthreads();

        // ---- scores ----
        float s[2][4];
#pragma unroll
        for (int i = 0; i < 2; i++)
#pragma unroll
            for (int j = 0; j < 4; j++) s[i][j] = 0.f;

        const float* q0p = &Qs[ty*2][0];
        const float* q1p = &Qs[ty*2 + 1][0];
#pragma unroll
        for (int k = 0; k < 64; k++) {
            const float4 kk4 = *(const float4*)&KsT[k][tx*4];
            const float q0 = q0p[k], q1 = q1p[k];
            s[0][0] = fmaf(q0, kk4.x, s[0][0]); s[0][1] = fmaf(q0, kk4.y, s[0][1]);
            s[0][2] = fmaf(q0, kk4.z, s[0][2]); s[0][3] = fmaf(q0, kk4.w, s[0][3]);
            s[1][0] = fmaf(q1, kk4.x, s[1][0]); s[1][1] = fmaf(q1, kk4.y, s[1][1]);
            s[1][2] = fmaf(q1, kk4.z, s[1][2]); s[1][3] = fmaf(q1, kk4.w, s[1][3]);
        }

        // ---- online softmax ----
#pragma unroll
        for (int ii = 0; ii < 2; ii++) {
            float mx = fmaxf(fmaxf(s[ii][0], s[ii][1]), fmaxf(s[ii][2], s[ii][3]));
            mx = fmaxf(mx, __shfl_xor_sync(0xffffffffu, mx, 1, 8));
            mx = fmaxf(mx, __shfl_xor_sync(0xffffffffu, mx, 2, 8));
            mx = fmaxf(mx, __shfl_xor_sync(0xffffffffu, mx, 4, 8));
            const float mnew = fmaxf(mi[ii], mx);
            const float corr = __expf(mi[ii] - mnew);
            float ps = 0.f;
#pragma unroll
            for (int j = 0; j < 4; j++) {
                const float p = __expf(s[ii][j] - mnew);
                Ps[ty*2 + ii][tx*4 + j] = p;
                ps += p;
            }
            ps += __shfl_xor_sync(0xffffffffu, ps, 1, 8);
            ps += __shfl_xor_sync(0xffffffffu, ps, 2, 8);
            ps += __shfl_xor_sync(0xffffffffu, ps, 4, 8);
            li[ii] = li[ii]*corr + ps;
            mi[ii] = mnew;
#pragma unroll
            for (int cc = 0; cc < 8; cc++) o[ii][cc] *= corr;
        }
        __syncthreads();

        // ---- PV ----
#pragma unroll
        for (int j = 0; j < 32; j++) {
            const float p0 = Ps[ty*2][j];
            const float p1 = Ps[ty*2 + 1][j];
            const float4 v0 = *(const float4*)&Vs[j][tx*8];
            const float4 v1 = *(const float4*)&Vs[j][tx*8 + 4];
            o[0][0] = fmaf(p0, v0.x, o[0][0]); o[0][1] = fmaf(p0, v0.y, o[0][1]);
            o[0][2] = fmaf(p0, v0.z, o[0][2]); o[0][3] = fmaf(p0, v0.w, o[0][3]);
            o[0][4] = fmaf(p0, v1.x, o[0][4]); o[0][5] = fmaf(p0, v1.y, o[0][5]);
            o[0][6] = fmaf(p0, v1.z, o[0][6]); o[0][7] = fmaf(p0, v1.w, o[0][7]);
            o[1][0] = fmaf(p1, v0.x, o[1][0]); o[1][1] = fmaf(p1, v0.y, o[1][1]);
            o[1][2] = fmaf(p1, v0.z, o[1][2]); o[1][3] = fmaf(p1, v0.w, o[1][3]);
            o[1][4] = fmaf(p1, v1.x, o[1][4]); o[1][5] = fmaf(p1, v1.y, o[1][5]);
            o[1][6] = fmaf(p1, v1.z, o[1][6]); o[1][7] = fmaf(p1, v1.w, o[1][7]);
        }
    }

    // ---- write context: Ctx[b*1024+i][h*64 + vd] ----
#pragma unroll
    for (int ii = 0; ii < 2; ii++) {
        const float inv = 1.0f / li[ii];
        const int i = qt*64 + ty*2 + ii;
        const size_t base = ((size_t)(b*SS + i))*DD + h*64 + tx*8;
        float4 w0 = make_float4(o[ii][0]*inv, o[ii][1]*inv, o[ii][2]*inv, o[ii][3]*inv);
        float4 w1 = make_float4(o[ii][4]*inv, o[ii][5]*inv, o[ii][6]*inv, o[ii][7]*inv);
        *(float4*)&g_Ctx[base]     = w0;
        *(float4*)&g_Ctx[base + 4] = w1;
    }
}

// ---------------------------------------------------------------------------
// Per-batch LayerNorm stats from the 64 CTA partials per batch (deterministic)
// ---------------------------------------------------------------------------
__global__ void finalize_stats()
{
    const int t = threadIdx.x;
    if (t < BB) {
        double s = 0.0, q = 0.0;
        for (int i = 0; i < 64; i++) {
            s += (double)g_psum[t*64 + i];
            q += (double)g_psq [t*64 + i];
        }
        const double n = (double)NELEM_PER_BATCH;
        const double mean = s / n;
        const double var  = q / n - mean*mean;
        g_mean[t] = (float)mean;
        g_rstd[t] = (float)(1.0 / sqrt(var + 1e-5));
    }
}

// ---------------------------------------------------------------------------
// y = (y - mean) * rstd * ln_w + ln_b   (float4 vectorized)
// ---------------------------------------------------------------------------
__global__ __launch_bounds__(512)
void ln_apply(const float* __restrict__ lnw, const float* __restrict__ lnb,
              float* __restrict__ out)
{
    const size_t i4 = (size_t)blockIdx.x * 512 + threadIdx.x;  // float4 index
    const size_t i  = i4 * 4;
    const int b     = (int)(i >> 20);
    const size_t sd = i & (size_t)(NELEM_PER_BATCH - 1);

    const float4 y = *(const float4*)&g_Y[i];
    const float4 w = *(const float4*)&lnw[sd];
    const float4 c = *(const float4*)&lnb[sd];
    const float mu = g_mean[b];
    const float rs = g_rstd[b];

    float4 r;
    r.x = (y.x - mu)*rs*w.x + c.x;
    r.y = (y.y - mu)*rs*w.y + c.y;
    r.z = (y.z - mu)*rs*w.z + c.z;
    r.w = (y.w - mu)*rs*w.w + c.w;
    *(float4*)&out[i] = r;
}

// ---------------------------------------------------------------------------
extern "C" void kernel_launch(void* const* d_in, const int* in_sizes, int n_in,
                              void* d_out, int out_size)
{
    const float* x   = (const float*)d_in[0];
    const float* Wqk = (const float*)d_in[1];
    const float* bqk = (const float*)d_in[2];
    const float* Wv  = (const float*)d_in[3];
    const float* bv  = (const float*)d_in[4];
    const float* Wo  = (const float*)d_in[5];
    const float* bo  = (const float*)d_in[6];
    const float* lnw = (const float*)d_in[7];
    const float* lnb = (const float*)d_in[8];
    float* out = (float*)d_out;

    gemm_mma<0><<<dim3(2048/128, MTOT/128), 256>>>(x, Wqk, bqk);   // q,k proj
    gemm_mma<1><<<dim3(1024/128, MTOT/128), 256>>>(x, Wv,  bv);    // v proj
    attn_k    <<<dim3(SS/64, HH, BB), 256>>>();                    // context
    gemm_mma<2><<<dim3(1024/128, MTOT/128), 256>>>(x, Wo,  bo);    // y + stats partials
    finalize_stats<<<1, 32>>>();
    ln_apply<<<(MTOT*DD/4)/512, 512>>>(lnw, lnb, out);
}

// round 5
// speedup vs baseline: 2.6039x; 1.9900x over previous
#include <cuda_runtime.h>
#include <math.h>
#include <stdint.h>

// Problem constants
#define BB   8
#define SS   1024
#define DD   1024
#define HH   16
#define KD   64
#define VD   64
#define MTOT (BB*SS)             // 8192
#define NELEM_PER_BATCH (SS*DD)  // 1048576

// ---------------------------------------------------------------------------
// Scratch (device globals; no dynamic allocation allowed)
// ---------------------------------------------------------------------------
__device__ float g_Q[(size_t)BB*HH*SS*KD];    // [b,h,s,kd]  32 MiB
__device__ float g_K[(size_t)BB*HH*SS*KD];    // [b,h,s,kd]  32 MiB
__device__ float g_V[(size_t)BB*HH*SS*VD];    // [b,h,s,vd]  32 MiB
__device__ float g_Ctx[(size_t)MTOT*DD];      // [m, h*64+vd] 32 MiB
__device__ float g_Y[(size_t)MTOT*DD];        // pre-LN y     32 MiB
__device__ float g_psum[512];
__device__ float g_psq[512];
__device__ float g_mean[BB];
__device__ float g_rstd[BB];

// ---------------------------------------------------------------------------
// TF32 helpers
// ---------------------------------------------------------------------------
__device__ __forceinline__ float f2tf(float f) {
    uint32_t u;
    asm("cvt.rna.tf32.f32 %0, %1;" : "=r"(u) : "f"(f));
    return __uint_as_float(u);
}
__device__ __forceinline__ float4 f2tf4(float4 v) {
    v.x = f2tf(v.x); v.y = f2tf(v.y); v.z = f2tf(v.z); v.w = f2tf(v.w);
    return v;
}

__device__ __forceinline__ void mma_tf32(float* c, const uint32_t* a, const uint32_t* b) {
    asm volatile(
        "mma.sync.aligned.m16n8k8.row.col.f32.tf32.tf32.f32 "
        "{%0,%1,%2,%3}, {%4,%5,%6,%7}, {%8,%9}, {%0,%1,%2,%3};"
        : "+f"(c[0]), "+f"(c[1]), "+f"(c[2]), "+f"(c[3])
        : "r"(a[0]), "r"(a[1]), "r"(a[2]), "r"(a[3]), "r"(b[0]), "r"(b[1]));
}

// ---------------------------------------------------------------------------
// TF32 tensor-core GEMM: C = A @ W^T (+ epilogue)
// ---------------------------------------------------------------------------
#define SKS 20

template<int EPI>
__global__ __launch_bounds__(256, 2)
void gemm_mma(const float* __restrict__ X, const float* __restrict__ W,
              const float* __restrict__ bias)
{
    __shared__ float As[128][SKS];
    __shared__ float Bs[128][SKS];
    __shared__ float rs[256];
    __shared__ float rq[256];

    const int tid = threadIdx.x;
    const int bm  = blockIdx.y * 128;
    const int bn  = blockIdx.x * 128;

    const float* A = (EPI == 2) ? g_Ctx : X;

    const int lr = tid >> 2;
    const int lc = (tid & 3) * 4;

    const float* aptr0 = A + (size_t)(bm + lr)      * 1024 + lc;
    const float* aptr1 = A + (size_t)(bm + lr + 64) * 1024 + lc;
    const float* bptr0 = W + (size_t)(bn + lr)      * 1024 + lc;
    const float* bptr1 = W + (size_t)(bn + lr + 64) * 1024 + lc;

    const int warp = tid >> 5;
    const int lane = tid & 31;
    const int wm   = (warp >> 2) * 64;
    const int wn   = (warp & 3) * 32;
    const int gid  = lane >> 2;
    const int tig  = lane & 3;

    float acc[4][4][4];
#pragma unroll
    for (int mt = 0; mt < 4; mt++)
#pragma unroll
        for (int nt = 0; nt < 4; nt++)
#pragma unroll
            for (int e = 0; e < 4; e++) acc[mt][nt][e] = 0.f;

    float4 a0 = *(const float4*)(aptr0);
    float4 a1 = *(const float4*)(aptr1);
    float4 b0 = *(const float4*)(bptr0);
    float4 b1 = *(const float4*)(bptr1);

#pragma unroll 1
    for (int kt = 0; kt < 1024; kt += 16) {
        *(float4*)&As[lr][lc]      = f2tf4(a0);
        *(float4*)&As[lr + 64][lc] = f2tf4(a1);
        *(float4*)&Bs[lr][lc]      = f2tf4(b0);
        *(float4*)&Bs[lr + 64][lc] = f2tf4(b1);
        __syncthreads();

        if (kt + 16 < 1024) {
            a0 = *(const float4*)(aptr0 + kt + 16);
            a1 = *(const float4*)(aptr1 + kt + 16);
            b0 = *(const float4*)(bptr0 + kt + 16);
            b1 = *(const float4*)(bptr1 + kt + 16);
        }

#pragma unroll
        for (int ks = 0; ks < 16; ks += 8) {
            uint32_t af[4][4];
            uint32_t bf[4][2];
#pragma unroll
            for (int mt = 0; mt < 4; mt++) {
                const int mrow = wm + mt * 16 + gid;
                af[mt][0] = __float_as_uint(As[mrow    ][ks + tig    ]);
                af[mt][1] = __float_as_uint(As[mrow + 8][ks + tig    ]);
                af[mt][2] = __float_as_uint(As[mrow    ][ks + tig + 4]);
                af[mt][3] = __float_as_uint(As[mrow + 8][ks + tig + 4]);
            }
#pragma unroll
            for (int nt = 0; nt < 4; nt++) {
                const int nrow = wn + nt * 8 + gid;
                bf[nt][0] = __float_as_uint(Bs[nrow][ks + tig    ]);
                bf[nt][1] = __float_as_uint(Bs[nrow][ks + tig + 4]);
            }
#pragma unroll
            for (int mt = 0; mt < 4; mt++)
#pragma unroll
                for (int nt = 0; nt < 4; nt++)
                    mma_tf32(acc[mt][nt], af[mt], bf[nt]);
        }
        __syncthreads();
    }

    float lsum = 0.f, lsq = 0.f;
#pragma unroll
    for (int mt = 0; mt < 4; mt++) {
#pragma unroll
        for (int e2 = 0; e2 < 2; e2++) {
            const int m    = bm + wm + mt * 16 + gid + e2 * 8;
            const int bidx = m >> 10;
            const int si   = m & 1023;
#pragma unroll
            for (int nt = 0; nt < 4; nt++) {
#pragma unroll
                for (int e1 = 0; e1 < 2; e1++) {
                    const int n = bn + wn + nt * 8 + tig * 2 + e1;
                    float val = acc[mt][nt][e2 * 2 + e1] + bias[n];
                    if (EPI == 0) {
                        const int kd  = n >> 5;
                        const int rem = n & 31;
                        const int h   = rem & 15;
                        const size_t dst = (((size_t)bidx*HH + h)*SS + si)*KD + kd;
                        if (rem < 16) g_Q[dst] = val; else g_K[dst] = val;
                    } else if (EPI == 1) {
                        const int vd = n >> 4;
                        const int h  = n & 15;
                        g_V[(((size_t)bidx*HH + h)*SS + si)*VD + vd] = val;
                    } else {
                        val += X[(size_t)m*1024 + n];
                        g_Y[(size_t)m*1024 + n] = val;
                        lsum += val;
                        lsq  += val * val;
                    }
                }
            }
        }
    }

    if (EPI == 2) {
        rs[tid] = lsum; rq[tid] = lsq;
        __syncthreads();
#pragma unroll
        for (int s = 128; s > 0; s >>= 1) {
            if (tid < s) { rs[tid] += rs[tid+s]; rq[tid] += rq[tid+s]; }
            __syncthreads();
        }
        if (tid == 0) {
            const int p = blockIdx.y * 8 + blockIdx.x;
            g_psum[p] = rs[0];
            g_psq[p]  = rq[0];
        }
    }
}

// ---------------------------------------------------------------------------
// Tensor-core flash attention. CTA = (b, h, 64 q-rows), 128 threads (4 warps).
// Warp w owns q-rows [16w,16w+16). 16 key tiles of 64, online softmax.
// QK^T and PV via m16n8k8.tf32; P stays in registers (quad shuffles remap
// C-frag cols {2t,2t+1} -> A-frag cols {t,t+4}).
//   Ks stride 68: B-frag banks 4*gid+tig -> conflict-free.
//   Vs stride 72: B-frag banks 8*tig+gid -> conflict-free.
// ---------------------------------------------------------------------------
__global__ __launch_bounds__(128, 2)
void attn_mma()
{
    __shared__ float Ks[64][68];   // [key][kd]  (also Q staging)
    __shared__ float Vs[64][72];   // [key][vd]

    const int tid   = threadIdx.x;
    const int warp  = tid >> 5;
    const int lane  = tid & 31;
    const int gid   = lane >> 2;
    const int tig   = lane & 3;
    const int qbase = lane & ~3;

    const int qt = blockIdx.x;
    const int h  = blockIdx.y;
    const int b  = blockIdx.z;
    const size_t bh = ((size_t)b*HH + h) * SS * KD;
    const float* Qg = g_Q + bh + (size_t)qt*64*KD;
    const float* Kg = g_K + bh;
    const float* Vg = g_V + bh;

    // loader mapping: thread -> (row, 8 float4 along the 64-wide row)
    const int lr = tid >> 1;        // 0..63
    const int lc = (tid & 1) * 8;   // float4 col base

    // ---- stage Q (pre-scaled by 1/sqrt(64)=0.125, tf32) then grab fragments
    {
        const float4* src = (const float4*)(Qg + (size_t)lr*KD);
#pragma unroll
        for (int i = 0; i < 8; i++) {
            float4 v = src[lc + i];
            v.x *= 0.125f; v.y *= 0.125f; v.z *= 0.125f; v.w *= 0.125f;
            *(float4*)&Ks[lr][(lc + i)*4] = f2tf4(v);
        }
    }
    __syncthreads();

    uint32_t qf[8][4];
    const int wq = warp * 16;
#pragma unroll
    for (int ks = 0; ks < 8; ks++) {
        qf[ks][0] = __float_as_uint(Ks[wq + gid    ][ks*8 + tig    ]);
        qf[ks][1] = __float_as_uint(Ks[wq + gid + 8][ks*8 + tig    ]);
        qf[ks][2] = __float_as_uint(Ks[wq + gid    ][ks*8 + tig + 4]);
        qf[ks][3] = __float_as_uint(Ks[wq + gid + 8][ks*8 + tig + 4]);
    }
    __syncthreads();

    // ---- load first K/V tile ----
    {
        const float4* kp = (const float4*)(Kg + (size_t)lr*KD);
        const float4* vp = (const float4*)(Vg + (size_t)lr*KD);
#pragma unroll
        for (int i = 0; i < 8; i++) {
            *(float4*)&Ks[lr][(lc + i)*4] = f2tf4(kp[lc + i]);
            *(float4*)&Vs[lr][(lc + i)*4] = f2tf4(vp[lc + i]);
        }
    }
    __syncthreads();

    float mi[2] = {-1e30f, -1e30f};
    float li[2] = {0.f, 0.f};
    float o[8][4];
#pragma unroll
    for (int nt = 0; nt < 8; nt++)
#pragma unroll
        for (int e = 0; e < 4; e++) o[nt][e] = 0.f;

#pragma unroll 1
    for (int j = 0; j < 16; j++) {
        // prefetch next K/V tile into registers (overlaps with MMAs below)
        float4 kr[8], vr[8];
        if (j < 15) {
            const float4* kp = (const float4*)(Kg + (size_t)(j + 1)*64*KD + (size_t)lr*KD);
            const float4* vp = (const float4*)(Vg + (size_t)(j + 1)*64*KD + (size_t)lr*KD);
#pragma unroll
            for (int i = 0; i < 8; i++) { kr[i] = kp[lc + i]; vr[i] = vp[lc + i]; }
        }

        // ---- S = Q K^T  (warp: 16x64) ----
        float sc[8][4];
#pragma unroll
        for (int nt = 0; nt < 8; nt++)
#pragma unroll
            for (int e = 0; e < 4; e++) sc[nt][e] = 0.f;

#pragma unroll
        for (int ks = 0; ks < 8; ks++) {
#pragma unroll
            for (int nt = 0; nt < 8; nt++) {
                uint32_t bf[2];
                bf[0] = __float_as_uint(Ks[nt*8 + gid][ks*8 + tig    ]);
                bf[1] = __float_as_uint(Ks[nt*8 + gid][ks*8 + tig + 4]);
                mma_tf32(sc[nt], qf[ks], bf);
            }
        }

        // ---- online softmax (rows gid and gid+8) ----
        float mx0 = -1e30f, mx1 = -1e30f;
#pragma unroll
        for (int nt = 0; nt < 8; nt++) {
            mx0 = fmaxf(mx0, fmaxf(sc[nt][0], sc[nt][1]));
            mx1 = fmaxf(mx1, fmaxf(sc[nt][2], sc[nt][3]));
        }
        mx0 = fmaxf(mx0, __shfl_xor_sync(0xffffffffu, mx0, 1));
        mx0 = fmaxf(mx0, __shfl_xor_sync(0xffffffffu, mx0, 2));
        mx1 = fmaxf(mx1, __shfl_xor_sync(0xffffffffu, mx1, 1));
        mx1 = fmaxf(mx1, __shfl_xor_sync(0xffffffffu, mx1, 2));

        const float mn0 = fmaxf(mi[0], mx0);
        const float mn1 = fmaxf(mi[1], mx1);
        const float c0  = __expf(mi[0] - mn0);
        const float c1  = __expf(mi[1] - mn1);

        float s0 = 0.f, s1 = 0.f;
#pragma unroll
        for (int nt = 0; nt < 8; nt++) {
            sc[nt][0] = __expf(sc[nt][0] - mn0); s0 += sc[nt][0];
            sc[nt][1] = __expf(sc[nt][1] - mn0); s0 += sc[nt][1];
            sc[nt][2] = __expf(sc[nt][2] - mn1); s1 += sc[nt][2];
            sc[nt][3] = __expf(sc[nt][3] - mn1); s1 += sc[nt][3];
        }
        s0 += __shfl_xor_sync(0xffffffffu, s0, 1);
        s0 += __shfl_xor_sync(0xffffffffu, s0, 2);
        s1 += __shfl_xor_sync(0xffffffffu, s1, 1);
        s1 += __shfl_xor_sync(0xffffffffu, s1, 2);

        li[0] = li[0]*c0 + s0;
        li[1] = li[1]*c1 + s1;
        mi[0] = mn0; mi[1] = mn1;
#pragma unroll
        for (int nt = 0; nt < 8; nt++) {
            o[nt][0] *= c0; o[nt][1] *= c0;
            o[nt][2] *= c1; o[nt][3] *= c1;
        }

        // ---- O += P V  (A-frags of P assembled by quad shuffles) ----
#pragma unroll
        for (int ks = 0; ks < 8; ks++) {
            const int src  = qbase + (tig >> 1);
            const int src2 = src + 2;
            const float v0 = __shfl_sync(0xffffffffu, sc[ks][0], src);
            const float v1 = __shfl_sync(0xffffffffu, sc[ks][1], src);
            const float x0 = __shfl_sync(0xffffffffu, sc[ks][2], src);
            const float x1 = __shfl_sync(0xffffffffu, sc[ks][3], src);
            const float w0 = __shfl_sync(0xffffffffu, sc[ks][0], src2);
            const float w1 = __shfl_sync(0xffffffffu, sc[ks][1], src2);
            const float y0 = __shfl_sync(0xffffffffu, sc[ks][2], src2);
            const float y1 = __shfl_sync(0xffffffffu, sc[ks][3], src2);
            uint32_t af[4];
            af[0] = __float_as_uint(f2tf((tig & 1) ? v1 : v0));   // (r0, key tig)
            af[1] = __float_as_uint(f2tf((tig & 1) ? x1 : x0));   // (r1, key tig)
            af[2] = __float_as_uint(f2tf((tig & 1) ? w1 : w0));   // (r0, key tig+4)
            af[3] = __float_as_uint(f2tf((tig & 1) ? y1 : y0));   // (r1, key tig+4)
#pragma unroll
            for (int nt = 0; nt < 8; nt++) {
                uint32_t bf[2];
                bf[0] = __float_as_uint(Vs[ks*8 + tig    ][nt*8 + gid]);
                bf[1] = __float_as_uint(Vs[ks*8 + tig + 4][nt*8 + gid]);
                mma_tf32(o[nt], af, bf);
            }
        }

        __syncthreads();   // all warps done reading Ks/Vs
        if (j < 15) {
#pragma unroll
            for (int i = 0; i < 8; i++) {
                *(float4*)&Ks[lr][(lc + i)*4] = f2tf4(kr[i]);
                *(float4*)&Vs[lr][(lc + i)*4] = f2tf4(vr[i]);
            }
        }
        __syncthreads();
    }

    // ---- epilogue: Ctx[b*1024 + s][h*64 + vd] ----
    const float inv0 = 1.0f / li[0];
    const float inv1 = 1.0f / li[1];
    const int r0 = qt*64 + wq + gid;
    const int r1 = r0 + 8;
#pragma unroll
    for (int nt = 0; nt < 8; nt++) {
        const int col = h*64 + nt*8 + tig*2;
        float2 u0 = make_float2(o[nt][0]*inv0, o[nt][1]*inv0);
        float2 u1 = make_float2(o[nt][2]*inv1, o[nt][3]*inv1);
        *(float2*)&g_Ctx[((size_t)(b*SS + r0))*DD + col] = u0;
        *(float2*)&g_Ctx[((size_t)(b*SS + r1))*DD + col] = u1;
    }
}

// ---------------------------------------------------------------------------
__global__ void finalize_stats()
{
    const int t = threadIdx.x;
    if (t < BB) {
        double s = 0.0, q = 0.0;
        for (int i = 0; i < 64; i++) {
            s += (double)g_psum[t*64 + i];
            q += (double)g_psq [t*64 + i];
        }
        const double n = (double)NELEM_PER_BATCH;
        const double mean = s / n;
        const double var  = q / n - mean*mean;
        g_mean[t] = (float)mean;
        g_rstd[t] = (float)(1.0 / sqrt(var + 1e-5));
    }
}

__global__ __launch_bounds__(512)
void ln_apply(const float* __restrict__ lnw, const float* __restrict__ lnb,
              float* __restrict__ out)
{
    const size_t i4 = (size_t)blockIdx.x * 512 + threadIdx.x;
    const size_t i  = i4 * 4;
    const int b     = (int)(i >> 20);
    const size_t sd = i & (size_t)(NELEM_PER_BATCH - 1);

    const float4 y = *(const float4*)&g_Y[i];
    const float4 w = *(const float4*)&lnw[sd];
    const float4 c = *(const float4*)&lnb[sd];
    const float mu = g_mean[b];
    const float rs = g_rstd[b];

    float4 r;
    r.x = (y.x - mu)*rs*w.x + c.x;
    r.y = (y.y - mu)*rs*w.y + c.y;
    r.z = (y.z - mu)*rs*w.z + c.z;
    r.w = (y.w - mu)*rs*w.w + c.w;
    *(float4*)&out[i] = r;
}

// ---------------------------------------------------------------------------
extern "C" void kernel_launch(void* const* d_in, const int* in_sizes, int n_in,
                              void* d_out, int out_size)
{
    const float* x   = (const float*)d_in[0];
    const float* Wqk = (const float*)d_in[1];
    const float* bqk = (const float*)d_in[2];
    const float* Wv  = (const float*)d_in[3];
    const float* bv  = (const float*)d_in[4];
    const float* Wo  = (const float*)d_in[5];
    const float* bo  = (const float*)d_in[6];
    const float* lnw = (const float*)d_in[7];
    const float* lnb = (const float*)d_in[8];
    float* out = (float*)d_out;

    gemm_mma<0><<<dim3(2048/128, MTOT/128), 256>>>(x, Wqk, bqk);   // q,k proj
    gemm_mma<1><<<dim3(1024/128, MTOT/128), 256>>>(x, Wv,  bv);    // v proj
    attn_mma   <<<dim3(SS/64, HH, BB), 128>>>();                   // context
    gemm_mma<2><<<dim3(1024/128, MTOT/128), 256>>>(x, Wo,  bo);    // y + stats
    finalize_stats<<<1, 32>>>();
    ln_apply<<<(MTOT*DD/4)/512, 512>>>(lnw, lnb, out);
}